// round 11
// baseline (speedup 1.0000x reference)
#include <cuda_runtime.h>
#include <cstdint>
#include <cstddef>

#define NB 32
#define NT 2048
#define ND 512
#define NROWS (NB*NT)   // 65536

// ---------------- scratch (static device arrays; no allocation) ----------------
__device__ float g_xn [(size_t)NROWS*ND];
__device__ float g_nh [(size_t)NROWS*ND];
__device__ float g_ifb[(size_t)NROWS*ND];
__device__ float g_hf [(size_t)NROWS*ND];
__device__ float g_h0 [(size_t)NROWS*ND];
__device__ float g_h1 [(size_t)NROWS*ND];

// ---------------- rmsnorm ----------------
__global__ __launch_bounds__(256) void rmsnorm_kernel(
    const float* __restrict__ x, const float* __restrict__ gamma,
    float* __restrict__ xn)
{
    int row = blockIdx.x * 8 + (threadIdx.x >> 5);
    int l = threadIdx.x & 31;
    const float4* xr = (const float4*)(x + (size_t)row * ND);
    const float4* gp = (const float4*)gamma;
    float4 v[4];
    float ss = 0.f;
#pragma unroll
    for (int i = 0; i < 4; i++) {
        v[i] = xr[l + 32*i];
        ss += v[i].x*v[i].x + v[i].y*v[i].y + v[i].z*v[i].z + v[i].w*v[i].w;
    }
#pragma unroll
    for (int o = 16; o > 0; o >>= 1) ss += __shfl_xor_sync(0xffffffffu, ss, o);
    float n = fmaxf(sqrtf(ss), 1e-12f);
    float s = 22.627416997969522f / n;
    float4* orow = (float4*)(xn + (size_t)row * ND);
#pragma unroll
    for (int i = 0; i < 4; i++) {
        float4 g4 = gp[l + 32*i];
        float4 o;
        o.x = v[i].x * s * (g4.x + 1.f);
        o.y = v[i].y * s * (g4.y + 1.f);
        o.z = v[i].z * s * (g4.z + 1.f);
        o.w = v[i].w * s * (g4.w + 1.f);
        orow[l + 32*i] = o;
    }
}

// ---------------- tf32 tensor-core GEMM (proven ~0.36ms): C = A @ W ----------------
__device__ __forceinline__ uint32_t f2tf(float f) {
    uint32_t u; asm("cvt.rna.tf32.f32 %0, %1;" : "=r"(u) : "f"(f)); return u;
}
__device__ __forceinline__ void mma1688(float c[4], const uint32_t a[4], const uint32_t b[2]) {
    asm volatile(
        "mma.sync.aligned.m16n8k8.row.col.f32.tf32.tf32.f32 "
        "{%0,%1,%2,%3},{%4,%5,%6,%7},{%8,%9},{%0,%1,%2,%3};"
        : "+f"(c[0]), "+f"(c[1]), "+f"(c[2]), "+f"(c[3])
        : "r"(a[0]), "r"(a[1]), "r"(a[2]), "r"(a[3]), "r"(b[0]), "r"(b[1]));
}

template<int ACT>
__global__ __launch_bounds__(256) void tgemm_kernel(
    const float* __restrict__ A, const float* __restrict__ W,
    float* __restrict__ C)
{
    __shared__ uint32_t As[2][16][136];
    __shared__ uint32_t Bs[2][16][136];
    const int tid = threadIdx.x;
    const int l   = tid & 31;
    const int wid = tid >> 5;
    const int wm  = wid & 3;
    const int wn  = wid >> 2;
    const int gid = l >> 2, tig = l & 3;

    const int am = tid >> 1;
    const int ak = (tid & 1) * 8;
    const int bk = tid >> 5;
    const int bn = (tid & 31) * 4;

    const float* Ap = A + ((size_t)blockIdx.x * 128 + am) * ND + ak;
    const float* Wp = W + (size_t)bk * ND + blockIdx.y * 128 + bn;

    float acc[2][8][4];
#pragma unroll
    for (int mt = 0; mt < 2; mt++)
#pragma unroll
        for (int nt = 0; nt < 8; nt++)
#pragma unroll
            for (int e = 0; e < 4; e++) acc[mt][nt][e] = 0.f;

    float4 pa0 = *(const float4*)(Ap);
    float4 pa1 = *(const float4*)(Ap + 4);
    float4 pb0 = *(const float4*)(Wp);
    float4 pb1 = *(const float4*)(Wp + (size_t)8 * ND);

    {
        As[0][ak+0][am] = f2tf(pa0.x); As[0][ak+1][am] = f2tf(pa0.y);
        As[0][ak+2][am] = f2tf(pa0.z); As[0][ak+3][am] = f2tf(pa0.w);
        As[0][ak+4][am] = f2tf(pa1.x); As[0][ak+5][am] = f2tf(pa1.y);
        As[0][ak+6][am] = f2tf(pa1.z); As[0][ak+7][am] = f2tf(pa1.w);
        uint4 u0 = make_uint4(f2tf(pb0.x), f2tf(pb0.y), f2tf(pb0.z), f2tf(pb0.w));
        uint4 u1 = make_uint4(f2tf(pb1.x), f2tf(pb1.y), f2tf(pb1.z), f2tf(pb1.w));
        *(uint4*)&Bs[0][bk][bn]     = u0;
        *(uint4*)&Bs[0][bk + 8][bn] = u1;
    }
    __syncthreads();

    for (int kt = 0; kt < 32; kt++) {
        const int cur = kt & 1;
        if (kt < 31) {
            const int k0 = (kt + 1) * 16;
            pa0 = *(const float4*)(Ap + k0);
            pa1 = *(const float4*)(Ap + k0 + 4);
            pb0 = *(const float4*)(Wp + (size_t)k0 * ND);
            pb1 = *(const float4*)(Wp + (size_t)(k0 + 8) * ND);
        }
#pragma unroll
        for (int ks = 0; ks < 16; ks += 8) {
            uint32_t af[2][4], bf[8][2];
#pragma unroll
            for (int mt = 0; mt < 2; mt++) {
                int m0 = wm * 32 + mt * 16 + gid;
                af[mt][0] = As[cur][ks + tig][m0];
                af[mt][1] = As[cur][ks + tig][m0 + 8];
                af[mt][2] = As[cur][ks + tig + 4][m0];
                af[mt][3] = As[cur][ks + tig + 4][m0 + 8];
            }
#pragma unroll
            for (int nt = 0; nt < 8; nt++) {
                int n0 = wn * 64 + nt * 8 + gid;
                bf[nt][0] = Bs[cur][ks + tig][n0];
                bf[nt][1] = Bs[cur][ks + tig + 4][n0];
            }
#pragma unroll
            for (int mt = 0; mt < 2; mt++)
#pragma unroll
                for (int nt = 0; nt < 8; nt++)
                    mma1688(acc[mt][nt], af[mt], bf[nt]);
        }
        if (kt < 31) {
            const int nxt = cur ^ 1;
            As[nxt][ak+0][am] = f2tf(pa0.x); As[nxt][ak+1][am] = f2tf(pa0.y);
            As[nxt][ak+2][am] = f2tf(pa0.z); As[nxt][ak+3][am] = f2tf(pa0.w);
            As[nxt][ak+4][am] = f2tf(pa1.x); As[nxt][ak+5][am] = f2tf(pa1.y);
            As[nxt][ak+6][am] = f2tf(pa1.z); As[nxt][ak+7][am] = f2tf(pa1.w);
            uint4 u0 = make_uint4(f2tf(pb0.x), f2tf(pb0.y), f2tf(pb0.z), f2tf(pb0.w));
            uint4 u1 = make_uint4(f2tf(pb1.x), f2tf(pb1.y), f2tf(pb1.z), f2tf(pb1.w));
            *(uint4*)&Bs[nxt][bk][bn]     = u0;
            *(uint4*)&Bs[nxt][bk + 8][bn] = u1;
        }
        __syncthreads();
    }

#pragma unroll
    for (int mt = 0; mt < 2; mt++) {
        int row = blockIdx.x * 128 + wm * 32 + mt * 16 + gid;
#pragma unroll
        for (int nt = 0; nt < 8; nt++) {
            int col = blockIdx.y * 128 + wn * 64 + nt * 8 + tig * 2;
            float v0 = acc[mt][nt][0], v1 = acc[mt][nt][1];
            float v2 = acc[mt][nt][2], v3 = acc[mt][nt][3];
            if (ACT == 1) { v0 = tanhf(v0); v1 = tanhf(v1); v2 = tanhf(v2); v3 = tanhf(v3); }
            *(float2*)(C + (size_t)row * ND + col)       = make_float2(v0, v1);
            *(float2*)(C + (size_t)(row + 8) * ND + col) = make_float2(v2, v3);
        }
    }
}

// ---------------- sequential LRU scan, v6 ----------------
// v5 plus: per-step cluster barrier replaced by mbarrier pipeline (2 mbarriers,
// count=64: one arrival per warp per CTA, issued by lane 0 after syncwarp);
// h stored duplicated as b64 {h,h} so FFMA2 operands load directly (no movs).
__global__ __launch_bounds__(512, 1) void scan_kernel(
    const float* __restrict__ nh, const float* __restrict__ ifg,
    const float* __restrict__ Whf, const float* __restrict__ bhf,
    float* __restrict__ hout)
{
    extern __shared__ float smem[];   // [0,64KB): bf16 W half; [64KB,+8KB): h dup double buf
    char* wsm = (char*)smem;
    unsigned long long* hbuf = (unsigned long long*)((char*)smem + 65536);
    __shared__ __align__(8) unsigned long long mbar[2];

    const int rank  = blockIdx.x & 3;
    const int batch = blockIdx.x >> 2;
    const int tid = threadIdx.x;
    const int w = tid >> 5;
    const int l = tid & 31;
    const int jc = rank * 128 + w * 8;

    // register half: k = l + 32*i (i<8), cols jc..jc+7 as 4 b64 pairs per i
    unsigned long long Wreg[8][4];
#pragma unroll
    for (int i = 0; i < 8; i++) {
        const float* p = Whf + (size_t)(l + 32*i) * ND + jc;
        float4 a = *(const float4*)p;
        float4 b = *(const float4*)(p + 4);
        asm("mov.b64 %0,{%1,%2};" : "=l"(Wreg[i][0]) : "f"(a.x), "f"(a.y));
        asm("mov.b64 %0,{%1,%2};" : "=l"(Wreg[i][1]) : "f"(a.z), "f"(a.w));
        asm("mov.b64 %0,{%1,%2};" : "=l"(Wreg[i][2]) : "f"(b.x), "f"(b.y));
        asm("mov.b64 %0,{%1,%2};" : "=l"(Wreg[i][3]) : "f"(b.z), "f"(b.w));
    }
    // smem half: k = 256 + l + 32*i, bf16x2 col pairs, slot (i+l)&7 in 128B block
    const uint32_t wbase = (uint32_t)__cvta_generic_to_shared(wsm) + (uint32_t)tid * 128u;
#pragma unroll
    for (int i = 0; i < 8; i++) {
        const float* p = Whf + (size_t)(256 + l + 32*i) * ND + jc;
        float4 a = *(const float4*)p;
        float4 b = *(const float4*)(p + 4);
        uint32_t u0, u1, u2, u3;
        asm("cvt.rn.bf16x2.f32 %0, %1, %2;" : "=r"(u0) : "f"(a.y), "f"(a.x));
        asm("cvt.rn.bf16x2.f32 %0, %1, %2;" : "=r"(u1) : "f"(a.w), "f"(a.z));
        asm("cvt.rn.bf16x2.f32 %0, %1, %2;" : "=r"(u2) : "f"(b.y), "f"(b.x));
        asm("cvt.rn.bf16x2.f32 %0, %1, %2;" : "=r"(u3) : "f"(b.w), "f"(b.z));
        asm volatile("st.shared.v4.b32 [%0], {%1,%2,%3,%4};"
                     :: "r"(wbase + (uint32_t)(((i + l) & 7) * 16)),
                        "r"(u0), "r"(u1), "r"(u2), "r"(u3) : "memory");
    }
    hbuf[tid] = 0ull;
    hbuf[tid + 512] = 0ull;

    const uint32_t hb = (uint32_t)__cvta_generic_to_shared(hbuf);
    const uint32_t mb = (uint32_t)__cvta_generic_to_shared(&mbar[0]);

    if (tid == 0) {
        asm volatile("mbarrier.init.shared.b64 [%0], %1;" :: "r"(mb),      "r"(64u) : "memory");
        asm volatile("mbarrier.init.shared.b64 [%0], %1;" :: "r"(mb + 8u), "r"(64u) : "memory");
    }

    // remote bases (all threads compute; cheap, uniform)
    uint32_t rhb[4], rmb[4];
#pragma unroll
    for (int rr = 0; rr < 4; rr++) {
        asm("mapa.shared::cluster.u32 %0, %1, %2;" : "=r"(rhb[rr]) : "r"(hb), "r"(rr));
        asm("mapa.shared::cluster.u32 %0, %1, %2;" : "=r"(rmb[rr]) : "r"(mb), "r"(rr));
    }

    // producer state: lanes with (l&3)==0 own column j = jc + (l>>2)
    const int isProd = ((l & 3) == 0);
    const int j = jc + (l >> 2);
    float bj = 0.f, h_prev = 0.f;
    const float *nhp = nullptr, *ifp = nullptr;
    float* hop = nullptr;
    if (isProd) {
        bj = bhf[j];
        size_t off = (size_t)batch * NT * ND + j;
        nhp = nh + off; ifp = ifg + off; hop = hout + off;
    }
    const uint32_t hoff0 = (uint32_t)(j * 8);           // buf 0 store offset
    const uint32_t hoff1 = (uint32_t)((512 + j) * 8);   // buf 1 store offset

    asm volatile("barrier.cluster.arrive.aligned;" ::: "memory");
    asm volatile("barrier.cluster.wait.aligned;"   ::: "memory");

    float nh_cur = 0.f, if_cur = 0.f;
    if (isProd) { nh_cur = nhp[0]; if_cur = ifp[0]; }

    const bool hi16 = (l & 16) != 0;
    const bool hi8  = (l & 8)  != 0;
    const bool hi4  = (l & 4)  != 0;

    uint32_t ph0 = 0, ph1 = 0;

    for (int t = 0; t < NT; t++) {
        const int cur = t & 1, nxt = cur ^ 1;
        const uint32_t hcur = hb + (uint32_t)(cur * 4096);
        float nh_nxt = 0.f, if_nxt = 0.f;
        if (isProd && t + 1 < NT) {
            nh_nxt = nhp[(size_t)(t+1) * ND];
            if_nxt = ifp[(size_t)(t+1) * ND];
        }
        unsigned long long a01 = 0ull, a23 = 0ull, a45 = 0ull, a67 = 0ull;
        // register half (h pre-duplicated b64)
#pragma unroll
        for (int i = 0; i < 8; i++) {
            unsigned long long hd;
            asm volatile("ld.shared.b64 %0,[%1];"
                         : "=l"(hd) : "r"(hcur + (uint32_t)((l + 32*i) * 8)));
            asm volatile("fma.rn.f32x2 %0, %1, %2, %0;" : "+l"(a01) : "l"(hd), "l"(Wreg[i][0]));
            asm volatile("fma.rn.f32x2 %0, %1, %2, %0;" : "+l"(a23) : "l"(hd), "l"(Wreg[i][1]));
            asm volatile("fma.rn.f32x2 %0, %1, %2, %0;" : "+l"(a45) : "l"(hd), "l"(Wreg[i][2]));
            asm volatile("fma.rn.f32x2 %0, %1, %2, %0;" : "+l"(a67) : "l"(hd), "l"(Wreg[i][3]));
        }
        // smem half (bf16 W)
#pragma unroll
        for (int i = 0; i < 8; i++) {
            unsigned long long hd;
            asm volatile("ld.shared.b64 %0,[%1];"
                         : "=l"(hd) : "r"(hcur + (uint32_t)((256 + l + 32*i) * 8)));
            uint32_t u0, u1, u2, u3;
            asm volatile("ld.shared.v4.b32 {%0,%1,%2,%3},[%4];"
                         : "=r"(u0), "=r"(u1), "=r"(u2), "=r"(u3)
                         : "r"(wbase + (uint32_t)(((i + l) & 7) * 16)));
            unsigned long long w01, w23, w45, w67;
            asm("{.reg .b32 lo,hi; shl.b32 lo,%1,16; and.b32 hi,%1,0xffff0000U; mov.b64 %0,{lo,hi};}"
                : "=l"(w01) : "r"(u0));
            asm("{.reg .b32 lo,hi; shl.b32 lo,%1,16; and.b32 hi,%1,0xffff0000U; mov.b64 %0,{lo,hi};}"
                : "=l"(w23) : "r"(u1));
            asm("{.reg .b32 lo,hi; shl.b32 lo,%1,16; and.b32 hi,%1,0xffff0000U; mov.b64 %0,{lo,hi};}"
                : "=l"(w45) : "r"(u2));
            asm("{.reg .b32 lo,hi; shl.b32 lo,%1,16; and.b32 hi,%1,0xffff0000U; mov.b64 %0,{lo,hi};}"
                : "=l"(w67) : "r"(u3));
            asm volatile("fma.rn.f32x2 %0, %1, %2, %0;" : "+l"(a01) : "l"(hd), "l"(w01));
            asm volatile("fma.rn.f32x2 %0, %1, %2, %0;" : "+l"(a23) : "l"(hd), "l"(w23));
            asm volatile("fma.rn.f32x2 %0, %1, %2, %0;" : "+l"(a45) : "l"(hd), "l"(w45));
            asm volatile("fma.rn.f32x2 %0, %1, %2, %0;" : "+l"(a67) : "l"(hd), "l"(w67));
        }
        // unpack
        float a0,a1,a2,a3,a4,a5,a6,a7;
        asm("mov.b64 {%0,%1},%2;" : "=f"(a0), "=f"(a1) : "l"(a01));
        asm("mov.b64 {%0,%1},%2;" : "=f"(a2), "=f"(a3) : "l"(a23));
        asm("mov.b64 {%0,%1},%2;" : "=f"(a4), "=f"(a5) : "l"(a45));
        asm("mov.b64 {%0,%1},%2;" : "=f"(a6), "=f"(a7) : "l"(a67));
        // log-tree reduction: 9 shfl
        float b0, b1, b2, b3;
        {
            float s0 = hi16 ? a0 : a4, k0 = hi16 ? a4 : a0;
            float s1 = hi16 ? a1 : a5, k1 = hi16 ? a5 : a1;
            float s2 = hi16 ? a2 : a6, k2 = hi16 ? a6 : a2;
            float s3 = hi16 ? a3 : a7, k3 = hi16 ? a7 : a3;
            b0 = k0 + __shfl_xor_sync(0xffffffffu, s0, 16);
            b1 = k1 + __shfl_xor_sync(0xffffffffu, s1, 16);
            b2 = k2 + __shfl_xor_sync(0xffffffffu, s2, 16);
            b3 = k3 + __shfl_xor_sync(0xffffffffu, s3, 16);
        }
        float d0, d1;
        {
            float s0 = hi8 ? b0 : b2, k0 = hi8 ? b2 : b0;
            float s1 = hi8 ? b1 : b3, k1 = hi8 ? b3 : b1;
            d0 = k0 + __shfl_xor_sync(0xffffffffu, s0, 8);
            d1 = k1 + __shfl_xor_sync(0xffffffffu, s1, 8);
        }
        float e;
        {
            float s = hi4 ? d0 : d1, k = hi4 ? d1 : d0;
            e = k + __shfl_xor_sync(0xffffffffu, s, 4);
        }
        e += __shfl_xor_sync(0xffffffffu, e, 2);
        e += __shfl_xor_sync(0xffffffffu, e, 1);
        // producer lane 4c holds full sum of col jc+c
        if (isProd) {
            float z = e + bj + if_cur;
            float g = 1.f / (1.f + __expf(-z));
            float hn = fmaf(g, nh_cur - h_prev, h_prev);
            hop[(size_t)t * ND] = hn;
            h_prev = hn;
            unsigned long long hd;
            asm("mov.b64 %0,{%1,%1};" : "=l"(hd) : "f"(hn));
            const uint32_t off = nxt ? hoff1 : hoff0;
            asm volatile("st.shared::cluster.b64 [%0], %1;" :: "r"(rhb[0] + off), "l"(hd) : "memory");
            asm volatile("st.shared::cluster.b64 [%0], %1;" :: "r"(rhb[1] + off), "l"(hd) : "memory");
            asm volatile("st.shared::cluster.b64 [%0], %1;" :: "r"(rhb[2] + off), "l"(hd) : "memory");
            asm volatile("st.shared::cluster.b64 [%0], %1;" :: "r"(rhb[3] + off), "l"(hd) : "memory");
        }
        __syncwarp();
        if (l == 0) {
            const uint32_t moff = (uint32_t)(nxt * 8);
            asm volatile("mbarrier.arrive.release.cluster.shared::cluster.b64 _, [%0];"
                         :: "r"(rmb[0] + moff) : "memory");
            asm volatile("mbarrier.arrive.release.cluster.shared::cluster.b64 _, [%0];"
                         :: "r"(rmb[1] + moff) : "memory");
            asm volatile("mbarrier.arrive.release.cluster.shared::cluster.b64 _, [%0];"
                         :: "r"(rmb[2] + moff) : "memory");
            asm volatile("mbarrier.arrive.release.cluster.shared::cluster.b64 _, [%0];"
                         :: "r"(rmb[3] + moff) : "memory");
        }
        // wait for buffer nxt to be fully published (64 arrivals)
        {
            const uint32_t wa = mb + (uint32_t)(nxt * 8);
            const uint32_t par = nxt ? ph1 : ph0;
            asm volatile(
                "{\n\t.reg .pred P;\n\t"
                "WL%=:\n\t"
                "mbarrier.try_wait.parity.acquire.cluster.shared::cta.b64 P, [%0], %1, 0x989680;\n\t"
                "@!P bra WL%=;\n\t}"
                :: "r"(wa), "r"(par) : "memory");
            if (nxt) ph1 ^= 1u; else ph0 ^= 1u;
        }
        nh_cur = nh_nxt; if_cur = if_nxt;
    }

    asm volatile("barrier.cluster.arrive.aligned;" ::: "memory");
    asm volatile("barrier.cluster.wait.aligned;"   ::: "memory");
}

// ---------------- gate cell combine + residual ----------------
__global__ __launch_bounds__(256) void combine_kernel(
    const float4* __restrict__ x,  const float4* __restrict__ xn,
    const float4* __restrict__ nh, const float4* __restrict__ ifb,
    const float4* __restrict__ hf, const float4* __restrict__ bhf,
    float4* __restrict__ out)
{
    size_t idx = (size_t)blockIdx.x * 256 + threadIdx.x;
    float4 xv = x[idx], xnv = xn[idx], nhv = nh[idx], iv = ifb[idx], hv = hf[idx];
    float4 bv = bhf[idx & 127];
    float4 o;
    { float z = hv.x + bv.x + iv.x; float g = 1.f/(1.f+__expf(-z)); o.x = xv.x + xnv.x + g*(nhv.x - xnv.x); }
    { float z = hv.y + bv.y + iv.y; float g = 1.f/(1.f+__expf(-z)); o.y = xv.y + xnv.y + g*(nhv.y - xnv.y); }
    { float z = hv.z + bv.z + iv.z; float g = 1.f/(1.f+__expf(-z)); o.z = xv.z + xnv.z + g*(nhv.z - xnv.z); }
    { float z = hv.w + bv.w + iv.w; float g = 1.f/(1.f+__expf(-z)); o.w = xv.w + xnv.w + g*(nhv.w - xnv.w); }
    out[idx] = o;
}

// ---------------- launch ----------------
static void launch_scan(const float* nh, const float* ifb,
                        const float* W, const float* b, float* ho)
{
    constexpr int SMEMB = 65536 + 8192;
    cudaFuncSetAttribute(scan_kernel, cudaFuncAttributeMaxDynamicSharedMemorySize, SMEMB);
    cudaLaunchConfig_t cfg = {};
    cfg.gridDim  = dim3(128, 1, 1);
    cfg.blockDim = dim3(512, 1, 1);
    cfg.dynamicSmemBytes = SMEMB;
    cfg.stream = 0;
    cudaLaunchAttribute attr;
    attr.id = cudaLaunchAttributeClusterDimension;
    attr.val.clusterDim.x = 4; attr.val.clusterDim.y = 1; attr.val.clusterDim.z = 1;
    cfg.attrs = &attr;
    cfg.numAttrs = 1;
    cudaLaunchKernelEx(&cfg, scan_kernel, nh, ifb, W, b, ho);
}

extern "C" void kernel_launch(void* const* d_in, const int* in_sizes, int n_in,
                              void* d_out, int out_size)
{
    const float* x     = (const float*)d_in[0];
    const float* gamma = (const float*)d_in[1];
    const float* gWn   = (const float*)d_in[2];
    const float* gWif  = (const float*)d_in[3];
    const float* gWhf  = (const float*)d_in[4];
    const float* gbhf  = (const float*)d_in[5];
    const float* l0Wn  = (const float*)d_in[6];
    const float* l0Wif = (const float*)d_in[7];
    const float* l0Whf = (const float*)d_in[8];
    const float* l0bhf = (const float*)d_in[9];
    const float* l1Wn  = (const float*)d_in[10];
    const float* l1Wif = (const float*)d_in[11];
    const float* l1Whf = (const float*)d_in[12];
    const float* l1bhf = (const float*)d_in[13];
    float* out = (float*)d_out;

    float *xn, *nh, *ifb, *hf, *h0, *h1;
    cudaGetSymbolAddress((void**)&xn,  g_xn);
    cudaGetSymbolAddress((void**)&nh,  g_nh);
    cudaGetSymbolAddress((void**)&ifb, g_ifb);
    cudaGetSymbolAddress((void**)&hf,  g_hf);
    cudaGetSymbolAddress((void**)&h0,  g_h0);
    cudaGetSymbolAddress((void**)&h1,  g_h1);

    dim3 gg(NROWS / 128, ND / 128);

    rmsnorm_kernel<<<NROWS / 8, 256>>>(x, gamma, xn);

    tgemm_kernel<1><<<gg, 256>>>(xn, l0Wn,  nh);
    tgemm_kernel<0><<<gg, 256>>>(xn, l0Wif, ifb);
    launch_scan(nh, ifb, l0Whf, l0bhf, h0);

    tgemm_kernel<1><<<gg, 256>>>(h0, l1Wn,  nh);
    tgemm_kernel<0><<<gg, 256>>>(h0, l1Wif, ifb);
    launch_scan(nh, ifb, l1Whf, l1bhf, h1);

    tgemm_kernel<1><<<gg, 256>>>(h1, gWn,  nh);
    tgemm_kernel<0><<<gg, 256>>>(h1, gWif, ifb);
    tgemm_kernel<0><<<gg, 256>>>(xn, gWhf, hf);

    combine_kernel<<<(NROWS * (ND/4)) / 256, 256>>>(
        (const float4*)x, (const float4*)xn, (const float4*)nh,
        (const float4*)ifb, (const float4*)hf, (const float4*)gbhf,
        (float4*)out);
}

// round 12
// speedup vs baseline: 1.5661x; 1.5661x over previous
#include <cuda_runtime.h>
#include <cstdint>
#include <cstddef>

#define NB 32
#define NT 2048
#define ND 512
#define NROWS (NB*NT)   // 65536

// ---------------- scratch (static device arrays; no allocation) ----------------
__device__ float g_xn [(size_t)NROWS*ND];
__device__ float g_nh [(size_t)NROWS*ND];
__device__ float g_ifb[(size_t)NROWS*ND];
__device__ float g_hf [(size_t)NROWS*ND];
__device__ float g_h0 [(size_t)NROWS*ND];
__device__ float g_h1 [(size_t)NROWS*ND];

// ---------------- rmsnorm ----------------
__global__ __launch_bounds__(256) void rmsnorm_kernel(
    const float* __restrict__ x, const float* __restrict__ gamma,
    float* __restrict__ xn)
{
    int row = blockIdx.x * 8 + (threadIdx.x >> 5);
    int l = threadIdx.x & 31;
    const float4* xr = (const float4*)(x + (size_t)row * ND);
    const float4* gp = (const float4*)gamma;
    float4 v[4];
    float ss = 0.f;
#pragma unroll
    for (int i = 0; i < 4; i++) {
        v[i] = xr[l + 32*i];
        ss += v[i].x*v[i].x + v[i].y*v[i].y + v[i].z*v[i].z + v[i].w*v[i].w;
    }
#pragma unroll
    for (int o = 16; o > 0; o >>= 1) ss += __shfl_xor_sync(0xffffffffu, ss, o);
    float n = fmaxf(sqrtf(ss), 1e-12f);
    float s = 22.627416997969522f / n;
    float4* orow = (float4*)(xn + (size_t)row * ND);
#pragma unroll
    for (int i = 0; i < 4; i++) {
        float4 g4 = gp[l + 32*i];
        float4 o;
        o.x = v[i].x * s * (g4.x + 1.f);
        o.y = v[i].y * s * (g4.y + 1.f);
        o.z = v[i].z * s * (g4.z + 1.f);
        o.w = v[i].w * s * (g4.w + 1.f);
        orow[l + 32*i] = o;
    }
}

// ---------------- bf16 tensor-core GEMM: C = A @ W, opt tanh ----------------
// BM=BN=128, BK=16, 256 threads (8 warps 4x2), warp tile 32x64, m16n8k16 bf16.
// k-pairs packed bf16x2; As2/Bs2 stride 136 (conflict-free fragment LDS).
__device__ __forceinline__ uint32_t fpack_bf(float lo, float hi) {
    uint32_t u; asm("cvt.rn.bf16x2.f32 %0, %1, %2;" : "=r"(u) : "f"(hi), "f"(lo)); return u;
}
__device__ __forceinline__ void mma_bf16(float c[4], const uint32_t a[4], const uint32_t b[2]) {
    asm volatile(
        "mma.sync.aligned.m16n8k16.row.col.f32.bf16.bf16.f32 "
        "{%0,%1,%2,%3},{%4,%5,%6,%7},{%8,%9},{%0,%1,%2,%3};"
        : "+f"(c[0]), "+f"(c[1]), "+f"(c[2]), "+f"(c[3])
        : "r"(a[0]), "r"(a[1]), "r"(a[2]), "r"(a[3]), "r"(b[0]), "r"(b[1]));
}

template<int ACT>
__global__ __launch_bounds__(256) void tgemm_kernel(
    const float* __restrict__ A, const float* __restrict__ W,
    float* __restrict__ C)
{
    __shared__ uint32_t As2[2][8][136];   // k-pair rows, bf16x2 of (2p, 2p+1)
    __shared__ uint32_t Bs2[2][8][136];
    const int tid = threadIdx.x;
    const int l   = tid & 31;
    const int wid = tid >> 5;
    const int wm  = wid & 3;
    const int wn  = wid >> 2;
    const int gid = l >> 2, tig = l & 3;

    const int am  = tid >> 1;          // 0..127
    const int akp = (tid & 1) * 4;     // pair offset 0 or 4 (k 0..7 / 8..15)
    const int bkp = tid >> 5;          // 0..7 -> k rows 2bkp, 2bkp+1
    const int bn  = (tid & 31) * 4;

    const float* Ap  = A + ((size_t)blockIdx.x * 128 + am) * ND + akp * 2;
    const float* Wp0 = W + (size_t)(2 * bkp) * ND + blockIdx.y * 128 + bn;
    const float* Wp1 = Wp0 + ND;

    float acc[2][8][4];
#pragma unroll
    for (int mt = 0; mt < 2; mt++)
#pragma unroll
        for (int nt = 0; nt < 8; nt++)
#pragma unroll
            for (int e = 0; e < 4; e++) acc[mt][nt][e] = 0.f;

    float4 pa0 = *(const float4*)(Ap);
    float4 pa1 = *(const float4*)(Ap + 4);
    float4 pb0 = *(const float4*)(Wp0);
    float4 pb1 = *(const float4*)(Wp1);

    {
        As2[0][akp+0][am] = fpack_bf(pa0.x, pa0.y);
        As2[0][akp+1][am] = fpack_bf(pa0.z, pa0.w);
        As2[0][akp+2][am] = fpack_bf(pa1.x, pa1.y);
        As2[0][akp+3][am] = fpack_bf(pa1.z, pa1.w);
        uint4 u = make_uint4(fpack_bf(pb0.x, pb1.x), fpack_bf(pb0.y, pb1.y),
                             fpack_bf(pb0.z, pb1.z), fpack_bf(pb0.w, pb1.w));
        *(uint4*)&Bs2[0][bkp][bn] = u;
    }
    __syncthreads();

    for (int kt = 0; kt < 32; kt++) {
        const int cur = kt & 1;
        if (kt < 31) {
            const int k0 = (kt + 1) * 16;
            pa0 = *(const float4*)(Ap + k0);
            pa1 = *(const float4*)(Ap + k0 + 4);
            pb0 = *(const float4*)(Wp0 + (size_t)k0 * ND);
            pb1 = *(const float4*)(Wp1 + (size_t)k0 * ND);
        }
        {
            uint32_t af[2][4], bf[8][2];
#pragma unroll
            for (int mt = 0; mt < 2; mt++) {
                int m0 = wm * 32 + mt * 16 + gid;
                af[mt][0] = As2[cur][tig][m0];
                af[mt][1] = As2[cur][tig][m0 + 8];
                af[mt][2] = As2[cur][tig + 4][m0];
                af[mt][3] = As2[cur][tig + 4][m0 + 8];
            }
#pragma unroll
            for (int nt = 0; nt < 8; nt++) {
                int n0 = wn * 64 + nt * 8 + gid;
                bf[nt][0] = Bs2[cur][tig][n0];
                bf[nt][1] = Bs2[cur][tig + 4][n0];
            }
#pragma unroll
            for (int mt = 0; mt < 2; mt++)
#pragma unroll
                for (int nt = 0; nt < 8; nt++)
                    mma_bf16(acc[mt][nt], af[mt], bf[nt]);
        }
        if (kt < 31) {
            const int nxt = cur ^ 1;
            As2[nxt][akp+0][am] = fpack_bf(pa0.x, pa0.y);
            As2[nxt][akp+1][am] = fpack_bf(pa0.z, pa0.w);
            As2[nxt][akp+2][am] = fpack_bf(pa1.x, pa1.y);
            As2[nxt][akp+3][am] = fpack_bf(pa1.z, pa1.w);
            uint4 u = make_uint4(fpack_bf(pb0.x, pb1.x), fpack_bf(pb0.y, pb1.y),
                                 fpack_bf(pb0.z, pb1.z), fpack_bf(pb0.w, pb1.w));
            *(uint4*)&Bs2[nxt][bkp][bn] = u;
        }
        __syncthreads();
    }

    // epilogue (same C fragment layout as m16n8k8)
#pragma unroll
    for (int mt = 0; mt < 2; mt++) {
        int row = blockIdx.x * 128 + wm * 32 + mt * 16 + gid;
#pragma unroll
        for (int nt = 0; nt < 8; nt++) {
            int col = blockIdx.y * 128 + wn * 64 + nt * 8 + tig * 2;
            float v0 = acc[mt][nt][0], v1 = acc[mt][nt][1];
            float v2 = acc[mt][nt][2], v3 = acc[mt][nt][3];
            if (ACT == 1) { v0 = tanhf(v0); v1 = tanhf(v1); v2 = tanhf(v2); v3 = tanhf(v3); }
            *(float2*)(C + (size_t)row * ND + col)       = make_float2(v0, v1);
            *(float2*)(C + (size_t)(row + 8) * ND + col) = make_float2(v2, v3);
        }
    }
}

// ---------------- sequential LRU scan (R10/v5 — best measured) ----------------
__global__ __launch_bounds__(512, 1) void scan_kernel(
    const float* __restrict__ nh, const float* __restrict__ ifg,
    const float* __restrict__ Whf, const float* __restrict__ bhf,
    float* __restrict__ hout)
{
    extern __shared__ float smem[];   // [0,64KB): bf16 W half; [64KB,+4KB): h double buf
    char*  wsm  = (char*)smem;
    float* hbuf = (float*)((char*)smem + 65536);

    const int rank  = blockIdx.x & 3;
    const int batch = blockIdx.x >> 2;
    const int tid = threadIdx.x;
    const int w = tid >> 5;
    const int l = tid & 31;
    const int jc = rank * 128 + w * 8;

    unsigned long long Wreg[8][4];
#pragma unroll
    for (int i = 0; i < 8; i++) {
        const float* p = Whf + (size_t)(l + 32*i) * ND + jc;
        float4 a = *(const float4*)p;
        float4 b = *(const float4*)(p + 4);
        asm("mov.b64 %0,{%1,%2};" : "=l"(Wreg[i][0]) : "f"(a.x), "f"(a.y));
        asm("mov.b64 %0,{%1,%2};" : "=l"(Wreg[i][1]) : "f"(a.z), "f"(a.w));
        asm("mov.b64 %0,{%1,%2};" : "=l"(Wreg[i][2]) : "f"(b.x), "f"(b.y));
        asm("mov.b64 %0,{%1,%2};" : "=l"(Wreg[i][3]) : "f"(b.z), "f"(b.w));
    }
    const uint32_t wbase = (uint32_t)__cvta_generic_to_shared(wsm) + (uint32_t)tid * 128u;
#pragma unroll
    for (int i = 0; i < 8; i++) {
        const float* p = Whf + (size_t)(256 + l + 32*i) * ND + jc;
        float4 a = *(const float4*)p;
        float4 b = *(const float4*)(p + 4);
        uint32_t u0, u1, u2, u3;
        asm("cvt.rn.bf16x2.f32 %0, %1, %2;" : "=r"(u0) : "f"(a.y), "f"(a.x));
        asm("cvt.rn.bf16x2.f32 %0, %1, %2;" : "=r"(u1) : "f"(a.w), "f"(a.z));
        asm("cvt.rn.bf16x2.f32 %0, %1, %2;" : "=r"(u2) : "f"(b.y), "f"(b.x));
        asm("cvt.rn.bf16x2.f32 %0, %1, %2;" : "=r"(u3) : "f"(b.w), "f"(b.z));
        asm volatile("st.shared.v4.b32 [%0], {%1,%2,%3,%4};"
                     :: "r"(wbase + (uint32_t)(((i + l) & 7) * 16)),
                        "r"(u0), "r"(u1), "r"(u2), "r"(u3) : "memory");
    }
    hbuf[tid] = 0.f;
    hbuf[tid + 512] = 0.f;

    const uint32_t hbase = (uint32_t)__cvta_generic_to_shared(hbuf);

    const int isProd = ((l & 3) == 0);
    const int j = jc + (l >> 2);
    float bj = 0.f, h_prev = 0.f;
    const float *nhp = nullptr, *ifp = nullptr;
    float* hop = nullptr;
    uint32_t raddr[2][4];
    if (isProd) {
        bj = bhf[j];
        size_t off = (size_t)batch * NT * ND + j;
        nhp = nh + off; ifp = ifg + off; hop = hout + off;
#pragma unroll
        for (int buf = 0; buf < 2; buf++) {
            uint32_t la = hbase + (uint32_t)((buf * 512 + j) * 4);
#pragma unroll
            for (int rr = 0; rr < 4; rr++)
                asm("mapa.shared::cluster.u32 %0, %1, %2;"
                    : "=r"(raddr[buf][rr]) : "r"(la), "r"(rr));
        }
    }

    asm volatile("barrier.cluster.arrive.aligned;" ::: "memory");
    asm volatile("barrier.cluster.wait.aligned;"   ::: "memory");

    float nh_cur = 0.f, if_cur = 0.f;
    if (isProd) { nh_cur = nhp[0]; if_cur = ifp[0]; }

    const bool hi16 = (l & 16) != 0;
    const bool hi8  = (l & 8)  != 0;
    const bool hi4  = (l & 4)  != 0;

    for (int t = 0; t < NT; t++) {
        const float* hr = hbuf + (t & 1) * 512;
        float nh_nxt = 0.f, if_nxt = 0.f;
        if (isProd && t + 1 < NT) {
            nh_nxt = nhp[(size_t)(t+1) * ND];
            if_nxt = ifp[(size_t)(t+1) * ND];
        }
        unsigned long long a01 = 0ull, a23 = 0ull, a45 = 0ull, a67 = 0ull;
#pragma unroll
        for (int i = 0; i < 8; i++) {
            float hk = hr[l + 32*i];
            unsigned long long hd;
            asm("mov.b64 %0,{%1,%1};" : "=l"(hd) : "f"(hk));
            asm volatile("fma.rn.f32x2 %0, %1, %2, %0;" : "+l"(a01) : "l"(hd), "l"(Wreg[i][0]));
            asm volatile("fma.rn.f32x2 %0, %1, %2, %0;" : "+l"(a23) : "l"(hd), "l"(Wreg[i][1]));
            asm volatile("fma.rn.f32x2 %0, %1, %2, %0;" : "+l"(a45) : "l"(hd), "l"(Wreg[i][2]));
            asm volatile("fma.rn.f32x2 %0, %1, %2, %0;" : "+l"(a67) : "l"(hd), "l"(Wreg[i][3]));
        }
#pragma unroll
        for (int i = 0; i < 8; i++) {
            float hk = hr[256 + l + 32*i];
            unsigned long long hd;
            asm("mov.b64 %0,{%1,%1};" : "=l"(hd) : "f"(hk));
            uint32_t u0, u1, u2, u3;
            asm volatile("ld.shared.v4.b32 {%0,%1,%2,%3},[%4];"
                         : "=r"(u0), "=r"(u1), "=r"(u2), "=r"(u3)
                         : "r"(wbase + (uint32_t)(((i + l) & 7) * 16)));
            unsigned long long w01, w23, w45, w67;
            asm("{.reg .b32 lo,hi; shl.b32 lo,%1,16; and.b32 hi,%1,0xffff0000U; mov.b64 %0,{lo,hi};}"
                : "=l"(w01) : "r"(u0));
            asm("{.reg .b32 lo,hi; shl.b32 lo,%1,16; and.b32 hi,%1,0xffff0000U; mov.b64 %0,{lo,hi};}"
                : "=l"(w23) : "r"(u1));
            asm("{.reg .b32 lo,hi; shl.b32 lo,%1,16; and.b32 hi,%1,0xffff0000U; mov.b64 %0,{lo,hi};}"
                : "=l"(w45) : "r"(u2));
            asm("{.reg .b32 lo,hi; shl.b32 lo,%1,16; and.b32 hi,%1,0xffff0000U; mov.b64 %0,{lo,hi};}"
                : "=l"(w67) : "r"(u3));
            asm volatile("fma.rn.f32x2 %0, %1, %2, %0;" : "+l"(a01) : "l"(hd), "l"(w01));
            asm volatile("fma.rn.f32x2 %0, %1, %2, %0;" : "+l"(a23) : "l"(hd), "l"(w23));
            asm volatile("fma.rn.f32x2 %0, %1, %2, %0;" : "+l"(a45) : "l"(hd), "l"(w45));
            asm volatile("fma.rn.f32x2 %0, %1, %2, %0;" : "+l"(a67) : "l"(hd), "l"(w67));
        }
        float a0,a1,a2,a3,a4,a5,a6,a7;
        asm("mov.b64 {%0,%1},%2;" : "=f"(a0), "=f"(a1) : "l"(a01));
        asm("mov.b64 {%0,%1},%2;" : "=f"(a2), "=f"(a3) : "l"(a23));
        asm("mov.b64 {%0,%1},%2;" : "=f"(a4), "=f"(a5) : "l"(a45));
        asm("mov.b64 {%0,%1},%2;" : "=f"(a6), "=f"(a7) : "l"(a67));
        float b0, b1, b2, b3;
        {
            float s0 = hi16 ? a0 : a4, k0 = hi16 ? a4 : a0;
            float s1 = hi16 ? a1 : a5, k1 = hi16 ? a5 : a1;
            float s2 = hi16 ? a2 : a6, k2 = hi16 ? a6 : a2;
            float s3 = hi16 ? a3 : a7, k3 = hi16 ? a7 : a3;
            b0 = k0 + __shfl_xor_sync(0xffffffffu, s0, 16);
            b1 = k1 + __shfl_xor_sync(0xffffffffu, s1, 16);
            b2 = k2 + __shfl_xor_sync(0xffffffffu, s2, 16);
            b3 = k3 + __shfl_xor_sync(0xffffffffu, s3, 16);
        }
        float d0, d1;
        {
            float s0 = hi8 ? b0 : b2, k0 = hi8 ? b2 : b0;
            float s1 = hi8 ? b1 : b3, k1 = hi8 ? b3 : b1;
            d0 = k0 + __shfl_xor_sync(0xffffffffu, s0, 8);
            d1 = k1 + __shfl_xor_sync(0xffffffffu, s1, 8);
        }
        float e;
        {
            float s = hi4 ? d0 : d1, k = hi4 ? d1 : d0;
            e = k + __shfl_xor_sync(0xffffffffu, s, 4);
        }
        e += __shfl_xor_sync(0xffffffffu, e, 2);
        e += __shfl_xor_sync(0xffffffffu, e, 1);
        if (isProd) {
            float z = e + bj + if_cur;
            float g = 1.f / (1.f + __expf(-z));
            float hn = fmaf(g, nh_cur - h_prev, h_prev);
            hop[(size_t)t * ND] = hn;
            h_prev = hn;
            const int nb = (t + 1) & 1;
            asm volatile("st.shared::cluster.f32 [%0], %1;" :: "r"(raddr[nb][0]), "f"(hn) : "memory");
            asm volatile("st.shared::cluster.f32 [%0], %1;" :: "r"(raddr[nb][1]), "f"(hn) : "memory");
            asm volatile("st.shared::cluster.f32 [%0], %1;" :: "r"(raddr[nb][2]), "f"(hn) : "memory");
            asm volatile("st.shared::cluster.f32 [%0], %1;" :: "r"(raddr[nb][3]), "f"(hn) : "memory");
        }
        nh_cur = nh_nxt; if_cur = if_nxt;
        asm volatile("barrier.cluster.arrive.aligned;" ::: "memory");
        asm volatile("barrier.cluster.wait.aligned;"   ::: "memory");
    }
}

// ---------------- gate cell combine + residual ----------------
__global__ __launch_bounds__(256) void combine_kernel(
    const float4* __restrict__ x,  const float4* __restrict__ xn,
    const float4* __restrict__ nh, const float4* __restrict__ ifb,
    const float4* __restrict__ hf, const float4* __restrict__ bhf,
    float4* __restrict__ out)
{
    size_t idx = (size_t)blockIdx.x * 256 + threadIdx.x;
    float4 xv = x[idx], xnv = xn[idx], nhv = nh[idx], iv = ifb[idx], hv = hf[idx];
    float4 bv = bhf[idx & 127];
    float4 o;
    { float z = hv.x + bv.x + iv.x; float g = 1.f/(1.f+__expf(-z)); o.x = xv.x + xnv.x + g*(nhv.x - xnv.x); }
    { float z = hv.y + bv.y + iv.y; float g = 1.f/(1.f+__expf(-z)); o.y = xv.y + xnv.y + g*(nhv.y - xnv.y); }
    { float z = hv.z + bv.z + iv.z; float g = 1.f/(1.f+__expf(-z)); o.z = xv.z + xnv.z + g*(nhv.z - xnv.z); }
    { float z = hv.w + bv.w + iv.w; float g = 1.f/(1.f+__expf(-z)); o.w = xv.w + xnv.w + g*(nhv.w - xnv.w); }
    out[idx] = o;
}

// ---------------- launch ----------------
static void launch_scan(const float* nh, const float* ifb,
                        const float* W, const float* b, float* ho)
{
    constexpr int SMEMB = 65536 + 4096;
    cudaFuncSetAttribute(scan_kernel, cudaFuncAttributeMaxDynamicSharedMemorySize, SMEMB);
    cudaLaunchConfig_t cfg = {};
    cfg.gridDim  = dim3(128, 1, 1);
    cfg.blockDim = dim3(512, 1, 1);
    cfg.dynamicSmemBytes = SMEMB;
    cfg.stream = 0;
    cudaLaunchAttribute attr;
    attr.id = cudaLaunchAttributeClusterDimension;
    attr.val.clusterDim.x = 4; attr.val.clusterDim.y = 1; attr.val.clusterDim.z = 1;
    cfg.attrs = &attr;
    cfg.numAttrs = 1;
    cudaLaunchKernelEx(&cfg, scan_kernel, nh, ifb, W, b, ho);
}

extern "C" void kernel_launch(void* const* d_in, const int* in_sizes, int n_in,
                              void* d_out, int out_size)
{
    const float* x     = (const float*)d_in[0];
    const float* gamma = (const float*)d_in[1];
    const float* gWn   = (const float*)d_in[2];
    const float* gWif  = (const float*)d_in[3];
    const float* gWhf  = (const float*)d_in[4];
    const float* gbhf  = (const float*)d_in[5];
    const float* l0Wn  = (const float*)d_in[6];
    const float* l0Wif = (const float*)d_in[7];
    const float* l0Whf = (const float*)d_in[8];
    const float* l0bhf = (const float*)d_in[9];
    const float* l1Wn  = (const float*)d_in[10];
    const float* l1Wif = (const float*)d_in[11];
    const float* l1Whf = (const float*)d_in[12];
    const float* l1bhf = (const float*)d_in[13];
    float* out = (float*)d_out;

    float *xn, *nh, *ifb, *hf, *h0, *h1;
    cudaGetSymbolAddress((void**)&xn,  g_xn);
    cudaGetSymbolAddress((void**)&nh,  g_nh);
    cudaGetSymbolAddress((void**)&ifb, g_ifb);
    cudaGetSymbolAddress((void**)&hf,  g_hf);
    cudaGetSymbolAddress((void**)&h0,  g_h0);
    cudaGetSymbolAddress((void**)&h1,  g_h1);

    dim3 gg(NROWS / 128, ND / 128);

    rmsnorm_kernel<<<NROWS / 8, 256>>>(x, gamma, xn);

    tgemm_kernel<1><<<gg, 256>>>(xn, l0Wn,  nh);
    tgemm_kernel<0><<<gg, 256>>>(xn, l0Wif, ifb);
    launch_scan(nh, ifb, l0Whf, l0bhf, h0);

    tgemm_kernel<1><<<gg, 256>>>(h0, l1Wn,  nh);
    tgemm_kernel<0><<<gg, 256>>>(h0, l1Wif, ifb);
    launch_scan(nh, ifb, l1Whf, l1bhf, h1);

    tgemm_kernel<1><<<gg, 256>>>(h1, gWn,  nh);
    tgemm_kernel<0><<<gg, 256>>>(h1, gWif, ifb);
    tgemm_kernel<0><<<gg, 256>>>(xn, gWhf, hf);

    combine_kernel<<<(NROWS * (ND/4)) / 256, 256>>>(
        (const float4*)x, (const float4*)xn, (const float4*)nh,
        (const float4*)ifb, (const float4*)hf, (const float4*)gbhf,
        (float4*)out);
}